// round 1
// baseline (speedup 1.0000x reference)
#include <cuda_runtime.h>
#include <math.h>

// Problem constants (B=2048, N=150 from reference; B derived from in_sizes)
#define NPART    150
#define ROWP     152            // padded row count (multiple of 4)
#define COLP     156            // padded row stride in floats: 156*4B=624B, 16B-aligned,
                                // and (156 mod 32)=28 -> 8 consecutive lanes' float4 reads
                                // cover all 32 banks exactly once (conflict-free LDS.128)
#define NCH      38             // float4 chunks covering j/i in [0,152)
#define NTHREADS 256
#define ITERS    100
#define EPSR     1e-16f
// eps = 0.05 ; work in base-2: SC = C / (eps*ln2); loss = eln2 * sum(2^(F+G-SC) * SC)
#define INV_ELN2 28.853900817779268f   // 1/(0.05*ln2)
#define ELN2     0.034657359027997264f // 0.05*ln2

__device__ float g_batch[8192];

__device__ __forceinline__ float ex2f(float x) {
    float r; asm("ex2.approx.ftz.f32 %0, %1;" : "=f"(r) : "f"(x)); return r;
}
__device__ __forceinline__ float lg2f_(float x) {
    float r; asm("lg2.approx.f32 %0, %1;" : "=f"(r) : "f"(x)); return r;
}

__device__ __forceinline__ float block_sum(float v, float* red, int tid) {
    red[tid] = v;
    __syncthreads();
    #pragma unroll
    for (int s = NTHREADS / 2; s > 0; s >>= 1) {
        if (tid < s) red[tid] += red[tid + s];
        __syncthreads();
    }
    float r = red[0];
    __syncthreads();
    return r;
}

extern __shared__ float smem[];

__global__ void __launch_bounds__(NTHREADS, 2)
sinkhorn_kernel(const float* __restrict__ p_rec, const float* __restrict__ p_tar)
{
    float* SC  = smem;                  // ROWP*COLP  (base-2-scaled cost, padded with 1e30)
    float* G2  = SC  + ROWP * COLP;     // ROWP  (g / (eps*ln2))
    float* F2  = G2  + ROWP;            // ROWP
    float* la2 = F2  + ROWP;            // log2(a+EPS)
    float* lb2 = la2 + ROWP;
    float* xe  = lb2 + ROWP;            // eta_rel / phi_rel of both clouds
    float* xp  = xe  + ROWP;
    float* ye  = xp  + ROWP;
    float* yp  = ye  + ROWP;
    float* red = yp  + ROWP;            // NTHREADS reduction scratch

    const int b   = blockIdx.x;
    const int tid = threadIdx.x;
    const float PI_F  = 3.14159265358979323846f;
    const float TWOPI = 6.28318530717958647692f;

    // ---- load particles ----
    float px = 0.f, py = 0.f, pz = 0.f, qx = 0.f, qy = 0.f, qz = 0.f;
    if (tid < NPART) {
        const float* p = p_rec + (size_t)b * NPART * 3 + tid * 3;
        px = p[0]; py = p[1]; pz = p[2];
        const float* q = p_tar + (size_t)b * NPART * 3 + tid * 3;
        qx = q[0]; qy = q[1]; qz = q[2];
    }

    // ---- jet sums (6 block reductions, one-time cost) ----
    float jx = block_sum(px, red, tid);
    float jy = block_sum(py, red, tid);
    float jz = block_sum(pz, red, tid);
    float kx = block_sum(qx, red, tid);
    float ky = block_sum(qy, red, tid);
    float kz = block_sum(qz, red, tid);

    // ---- polar-rel coordinates ----
    float jpt  = sqrtf(jx * jx + jy * jy + EPSR);
    float jphi = atan2f(jy + EPSR, jx + EPSR);
    float jeta = asinhf(jz / (jpt + EPSR));
    float kpt  = sqrtf(kx * kx + ky * ky + EPSR);
    float kphi = atan2f(ky + EPSR, kx + EPSR);
    float keta = asinhf(kz / (kpt + EPSR));

    float ppt  = sqrtf(px * px + py * py + EPSR);
    float pphi = atan2f(py + EPSR, px + EPSR);
    float peta = asinhf(pz / (ppt + EPSR));
    float qpt  = sqrtf(qx * qx + qy * qy + EPSR);
    float qphi = atan2f(qy + EPSR, qx + EPSR);
    float qeta = asinhf(qz / (qpt + EPSR));

    float per = peta - jeta;
    float dpp = pphi - jphi + PI_F;
    float ppr = fmodf(dpp, TWOPI); if (ppr < 0.f) ppr += TWOPI; ppr -= PI_F;
    float pptr = ppt / (jpt + EPSR);

    float qer = qeta - keta;
    float dqq = qphi - kphi + PI_F;
    float qpr = fmodf(dqq, TWOPI); if (qpr < 0.f) qpr += TWOPI; qpr -= PI_F;
    float qptr = qpt / (kpt + EPSR);

    // ---- normalized marginals (log2 domain) ----
    float Sa = block_sum(tid < NPART ? pptr : 0.f, red, tid);
    float Sb = block_sum(tid < NPART ? qptr : 0.f, red, tid);

    if (tid < NPART) {
        xe[tid] = per;  xp[tid] = ppr;
        ye[tid] = qer;  yp[tid] = qpr;
        la2[tid] = lg2f_(pptr / (Sa + EPSR) + EPSR);
        lb2[tid] = lg2f_(qptr / (Sb + EPSR) + EPSR);
    }
    if (tid < ROWP) { G2[tid] = 0.f; F2[tid] = 0.f; }
    __syncthreads();

    // ---- cost matrix: SC = DeltaR / (eps*ln2); padding = +1e30 (kills pad terms) ----
    for (int idx = tid; idx < ROWP * COLP; idx += NTHREADS) {
        int i = idx / COLP;
        int j = idx - i * COLP;
        float v = 1e30f;
        if (i < NPART && j < NPART) {
            float de = xe[i] - ye[j];
            float dp = xp[i] - yp[j];
            v = sqrtf(de * de + dp * dp + EPSR) * INV_ELN2;
        }
        SC[idx] = v;
    }
    __syncthreads();

    // ---- Sinkhorn loop (log domain, base-2) ----
    for (int it = 0; it < ITERS; ++it) {
        // F-update: row-wise, thread i owns row i, float4 LDS on SC row & G2
        if (tid < NPART) {
            const float4* crow = (const float4*)(SC + tid * COLP);
            const float4* gp   = (const float4*)G2;
            float m0 = -3.4e38f, m1 = -3.4e38f, m2 = -3.4e38f, m3 = -3.4e38f;
            #pragma unroll 2
            for (int k = 0; k < NCH; ++k) {
                float4 c = crow[k]; float4 g = gp[k];
                m0 = fmaxf(m0, g.x - c.x); m1 = fmaxf(m1, g.y - c.y);
                m2 = fmaxf(m2, g.z - c.z); m3 = fmaxf(m3, g.w - c.w);
            }
            float m = fmaxf(fmaxf(m0, m1), fmaxf(m2, m3));
            float s0 = 0.f, s1 = 0.f, s2 = 0.f, s3 = 0.f;
            #pragma unroll 2
            for (int k = 0; k < NCH; ++k) {
                float4 c = crow[k]; float4 g = gp[k];
                s0 += ex2f(g.x - c.x - m); s1 += ex2f(g.y - c.y - m);
                s2 += ex2f(g.z - c.z - m); s3 += ex2f(g.w - c.w - m);
            }
            F2[tid] = la2[tid] - (m + lg2f_((s0 + s1) + (s2 + s3)));
        }
        __syncthreads();

        // G-update: column-wise, thread j owns column j (consecutive banks: conflict-free)
        if (tid < NPART) {
            const float*  ccol = SC + tid;
            const float4* fp   = (const float4*)F2;
            float m0 = -3.4e38f, m1 = -3.4e38f, m2 = -3.4e38f, m3 = -3.4e38f;
            #pragma unroll 2
            for (int k = 0; k < NCH; ++k) {
                float4 f = fp[k];
                const float* cb = ccol + 4 * k * COLP;
                m0 = fmaxf(m0, f.x - cb[0]);
                m1 = fmaxf(m1, f.y - cb[COLP]);
                m2 = fmaxf(m2, f.z - cb[2 * COLP]);
                m3 = fmaxf(m3, f.w - cb[3 * COLP]);
            }
            float m = fmaxf(fmaxf(m0, m1), fmaxf(m2, m3));
            float s0 = 0.f, s1 = 0.f, s2 = 0.f, s3 = 0.f;
            #pragma unroll 2
            for (int k = 0; k < NCH; ++k) {
                float4 f = fp[k];
                const float* cb = ccol + 4 * k * COLP;
                s0 += ex2f(f.x - cb[0]        - m);
                s1 += ex2f(f.y - cb[COLP]     - m);
                s2 += ex2f(f.z - cb[2 * COLP] - m);
                s3 += ex2f(f.w - cb[3 * COLP] - m);
            }
            G2[tid] = lb2[tid] - (m + lg2f_((s0 + s1) + (s2 + s3)));
        }
        __syncthreads();
    }

    // ---- loss = eln2 * sum_ij 2^(F+G-SC) * SC ----
    float part = 0.f;
    if (tid < NPART) {
        const float4* crow = (const float4*)(SC + tid * COLP);
        const float4* gp   = (const float4*)G2;
        float fi = F2[tid];
        float p0 = 0.f, p1 = 0.f, p2 = 0.f, p3 = 0.f;
        #pragma unroll 2
        for (int k = 0; k < NCH; ++k) {
            float4 c = crow[k]; float4 g = gp[k];
            p0 += ex2f(fi + g.x - c.x) * c.x;   // pad: ex2(-1e30)=0 -> 0*1e30=0
            p1 += ex2f(fi + g.y - c.y) * c.y;
            p2 += ex2f(fi + g.z - c.z) * c.z;
            p3 += ex2f(fi + g.w - c.w) * c.w;
        }
        part = (p0 + p1) + (p2 + p3);
    }
    float tot = block_sum(part, red, tid);
    if (tid == 0) g_batch[b] = tot * ELN2;
}

__global__ void reduce_kernel(float* __restrict__ out, int B)
{
    __shared__ float red[256];
    int tid = threadIdx.x;
    float s = 0.f;
    for (int i = tid; i < B; i += 256) s += g_batch[i];
    red[tid] = s;
    __syncthreads();
    #pragma unroll
    for (int k = 128; k > 0; k >>= 1) {
        if (tid < k) red[tid] += red[tid + k];
        __syncthreads();
    }
    if (tid == 0) out[0] = red[0];
}

extern "C" void kernel_launch(void* const* d_in, const int* in_sizes, int n_in,
                              void* d_out, int out_size)
{
    const float* p_rec = (const float*)d_in[0];
    const float* p_tar = (const float*)d_in[1];
    int B = in_sizes[0] / (NPART * 3);
    if (B > 8192) B = 8192;

    size_t smem_bytes = (size_t)(ROWP * COLP + 8 * ROWP + NTHREADS) * sizeof(float);
    cudaFuncSetAttribute(sinkhorn_kernel,
                         cudaFuncAttributeMaxDynamicSharedMemorySize,
                         (int)smem_bytes);
    sinkhorn_kernel<<<B, NTHREADS, smem_bytes>>>(p_rec, p_tar);
    reduce_kernel<<<1, 256>>>((float*)d_out, B);
}

// round 2
// speedup vs baseline: 1.3950x; 1.3950x over previous
#include <cuda_runtime.h>
#include <math.h>

// Problem constants (B=2048, N=150 from reference; B derived from in_sizes)
#define NPART    150
#define ROWP     152            // padded row count (multiple of 4)
#define COLP     156            // padded row stride in floats: 624B, 16B-aligned;
                                // (156 mod 32)=28 -> conflict-free LDS.128 rows and
                                // conflict-free scalar column walks
#define NCH      38             // float4 chunks covering [0,152)
#define NTHREADS 256
#define ITERS    100
#define PEEL     6              // first PEEL iterations use classic 2-pass LSE
#define EPSR     1e-16f
// eps = 0.05 ; base-2 units: SC = C/(eps*ln2); loss = eln2 * sum(2^(F+G-SC) * SC)
#define INV_ELN2 28.853900817779268f   // 1/(0.05*ln2)
#define ELN2     0.034657359027997264f // 0.05*ln2

__device__ float g_batch[8192];

__device__ __forceinline__ float ex2f(float x) {
    float r; asm("ex2.approx.ftz.f32 %0, %1;" : "=f"(r) : "f"(x)); return r;
}
__device__ __forceinline__ float lg2f_(float x) {
    float r; asm("lg2.approx.f32 %0, %1;" : "=f"(r) : "f"(x)); return r;
}

__device__ __forceinline__ float block_sum(float v, float* red, int tid) {
    red[tid] = v;
    __syncthreads();
    #pragma unroll
    for (int s = NTHREADS / 2; s > 0; s >>= 1) {
        if (tid < s) red[tid] += red[tid + s];
        __syncthreads();
    }
    float r = red[0];
    __syncthreads();
    return r;
}

extern __shared__ float smem[];

__global__ void __launch_bounds__(NTHREADS, 2)
sinkhorn_kernel(const float* __restrict__ p_rec, const float* __restrict__ p_tar)
{
    float* SC  = smem;                  // ROWP*COLP  base-2-scaled cost (pad = 1e30)
    float* G2  = SC  + ROWP * COLP;
    float* F2  = G2  + ROWP;
    float* la2 = F2  + ROWP;
    float* lb2 = la2 + ROWP;
    float* Mf  = lb2 + ROWP;            // previous row-max centers (F side)
    float* Mg  = Mf  + ROWP;            // previous col-max centers (G side)
    float* xe  = Mg  + ROWP;
    float* xp  = xe  + ROWP;
    float* ye  = xp  + ROWP;
    float* yp  = ye  + ROWP;
    float* red = yp  + ROWP;            // NTHREADS reduction scratch

    const int b   = blockIdx.x;
    const int tid = threadIdx.x;
    const float PI_F  = 3.14159265358979323846f;
    const float TWOPI = 6.28318530717958647692f;

    // ---- load particles ----
    float px = 0.f, py = 0.f, pz = 0.f, qx = 0.f, qy = 0.f, qz = 0.f;
    if (tid < NPART) {
        const float* p = p_rec + (size_t)b * NPART * 3 + tid * 3;
        px = p[0]; py = p[1]; pz = p[2];
        const float* q = p_tar + (size_t)b * NPART * 3 + tid * 3;
        qx = q[0]; qy = q[1]; qz = q[2];
    }

    // ---- jet sums ----
    float jx = block_sum(px, red, tid);
    float jy = block_sum(py, red, tid);
    float jz = block_sum(pz, red, tid);
    float kx = block_sum(qx, red, tid);
    float ky = block_sum(qy, red, tid);
    float kz = block_sum(qz, red, tid);

    // ---- polar-rel coordinates ----
    float jpt  = sqrtf(jx * jx + jy * jy + EPSR);
    float jphi = atan2f(jy + EPSR, jx + EPSR);
    float jeta = asinhf(jz / (jpt + EPSR));
    float kpt  = sqrtf(kx * kx + ky * ky + EPSR);
    float kphi = atan2f(ky + EPSR, kx + EPSR);
    float keta = asinhf(kz / (kpt + EPSR));

    float ppt  = sqrtf(px * px + py * py + EPSR);
    float pphi = atan2f(py + EPSR, px + EPSR);
    float peta = asinhf(pz / (ppt + EPSR));
    float qpt  = sqrtf(qx * qx + qy * qy + EPSR);
    float qphi = atan2f(qy + EPSR, qx + EPSR);
    float qeta = asinhf(qz / (qpt + EPSR));

    float per = peta - jeta;
    float dpp = pphi - jphi + PI_F;
    float ppr = fmodf(dpp, TWOPI); if (ppr < 0.f) ppr += TWOPI; ppr -= PI_F;
    float pptr = ppt / (jpt + EPSR);

    float qer = qeta - keta;
    float dqq = qphi - kphi + PI_F;
    float qpr = fmodf(dqq, TWOPI); if (qpr < 0.f) qpr += TWOPI; qpr -= PI_F;
    float qptr = qpt / (kpt + EPSR);

    // ---- normalized marginals (log2 domain) ----
    float Sa = block_sum(tid < NPART ? pptr : 0.f, red, tid);
    float Sb = block_sum(tid < NPART ? qptr : 0.f, red, tid);

    if (tid < NPART) {
        xe[tid] = per;  xp[tid] = ppr;
        ye[tid] = qer;  yp[tid] = qpr;
        la2[tid] = lg2f_(pptr / (Sa + EPSR) + EPSR);
        lb2[tid] = lg2f_(qptr / (Sb + EPSR) + EPSR);
    }
    if (tid < ROWP) { G2[tid] = 0.f; F2[tid] = 0.f; Mf[tid] = 0.f; Mg[tid] = 0.f; }
    __syncthreads();

    // ---- cost matrix (pad = 1e30 kills pad terms via ex2 underflow) ----
    for (int idx = tid; idx < ROWP * COLP; idx += NTHREADS) {
        int i = idx / COLP;
        int j = idx - i * COLP;
        float v = 1e30f;
        if (i < NPART && j < NPART) {
            float de = xe[i] - ye[j];
            float dp = xp[i] - yp[j];
            v = sqrtf(de * de + dp * dp + EPSR) * INV_ELN2;
        }
        SC[idx] = v;
    }
    __syncthreads();

    // ---- Sinkhorn loop (log domain, base-2) ----
    for (int it = 0; it < ITERS; ++it) {
        const bool twopass = (it < PEEL);

        // ---------- F-update: thread i owns row i (float4 LDS) ----------
        if (tid < NPART) {
            const float4* crow = (const float4*)(SC + tid * COLP);
            const float4* gp   = (const float4*)G2;
            float m;
            if (twopass) {
                float m0 = -3.4e38f, m1 = -3.4e38f, m2 = -3.4e38f, m3 = -3.4e38f;
                #pragma unroll 2
                for (int k = 0; k < NCH; ++k) {
                    float4 c = crow[k]; float4 g = gp[k];
                    m0 = fmaxf(m0, g.x - c.x); m1 = fmaxf(m1, g.y - c.y);
                    m2 = fmaxf(m2, g.z - c.z); m3 = fmaxf(m3, g.w - c.w);
                }
                m = fmaxf(fmaxf(m0, m1), fmaxf(m2, m3));
                float s0 = 0.f, s1 = 0.f, s2 = 0.f, s3 = 0.f;
                #pragma unroll 2
                for (int k = 0; k < NCH; ++k) {
                    float4 c = crow[k]; float4 g = gp[k];
                    s0 += ex2f(g.x - c.x - m); s1 += ex2f(g.y - c.y - m);
                    s2 += ex2f(g.z - c.z - m); s3 += ex2f(g.w - c.w - m);
                }
                F2[tid] = la2[tid] - (m + lg2f_((s0 + s1) + (s2 + s3)));
                Mf[tid] = m;
            } else {
                // one-pass: center on previous iteration's max, track honest max
                m = Mf[tid];
                float m0 = -3.4e38f, m1 = -3.4e38f, m2 = -3.4e38f, m3 = -3.4e38f;
                float s0 = 0.f, s1 = 0.f, s2 = 0.f, s3 = 0.f;
                #pragma unroll 2
                for (int k = 0; k < NCH; ++k) {
                    float4 c = crow[k]; float4 g = gp[k];
                    float t0 = g.x - c.x, t1 = g.y - c.y;
                    float t2 = g.z - c.z, t3 = g.w - c.w;
                    m0 = fmaxf(m0, t0); s0 += ex2f(t0 - m);
                    m1 = fmaxf(m1, t1); s1 += ex2f(t1 - m);
                    m2 = fmaxf(m2, t2); s2 += ex2f(t2 - m);
                    m3 = fmaxf(m3, t3); s3 += ex2f(t3 - m);
                }
                float s = fmaxf((s0 + s1) + (s2 + s3), 1e-30f); // -inf guard
                F2[tid] = la2[tid] - (m + lg2f_(s));
                Mf[tid] = fmaxf(fmaxf(m0, m1), fmaxf(m2, m3));
            }
        }
        __syncthreads();

        // ---------- G-update: thread j owns column j (conflict-free stride) ----------
        if (tid < NPART) {
            const float*  ccol = SC + tid;
            const float4* fp   = (const float4*)F2;
            float m;
            if (twopass) {
                float m0 = -3.4e38f, m1 = -3.4e38f, m2 = -3.4e38f, m3 = -3.4e38f;
                #pragma unroll 2
                for (int k = 0; k < NCH; ++k) {
                    float4 f = fp[k];
                    const float* cb = ccol + 4 * k * COLP;
                    m0 = fmaxf(m0, f.x - cb[0]);
                    m1 = fmaxf(m1, f.y - cb[COLP]);
                    m2 = fmaxf(m2, f.z - cb[2 * COLP]);
                    m3 = fmaxf(m3, f.w - cb[3 * COLP]);
                }
                m = fmaxf(fmaxf(m0, m1), fmaxf(m2, m3));
                float s0 = 0.f, s1 = 0.f, s2 = 0.f, s3 = 0.f;
                #pragma unroll 2
                for (int k = 0; k < NCH; ++k) {
                    float4 f = fp[k];
                    const float* cb = ccol + 4 * k * COLP;
                    s0 += ex2f(f.x - cb[0]        - m);
                    s1 += ex2f(f.y - cb[COLP]     - m);
                    s2 += ex2f(f.z - cb[2 * COLP] - m);
                    s3 += ex2f(f.w - cb[3 * COLP] - m);
                }
                G2[tid] = lb2[tid] - (m + lg2f_((s0 + s1) + (s2 + s3)));
                Mg[tid] = m;
            } else {
                m = Mg[tid];
                float m0 = -3.4e38f, m1 = -3.4e38f, m2 = -3.4e38f, m3 = -3.4e38f;
                float s0 = 0.f, s1 = 0.f, s2 = 0.f, s3 = 0.f;
                #pragma unroll 2
                for (int k = 0; k < NCH; ++k) {
                    float4 f = fp[k];
                    const float* cb = ccol + 4 * k * COLP;
                    float t0 = f.x - cb[0];
                    float t1 = f.y - cb[COLP];
                    float t2 = f.z - cb[2 * COLP];
                    float t3 = f.w - cb[3 * COLP];
                    m0 = fmaxf(m0, t0); s0 += ex2f(t0 - m);
                    m1 = fmaxf(m1, t1); s1 += ex2f(t1 - m);
                    m2 = fmaxf(m2, t2); s2 += ex2f(t2 - m);
                    m3 = fmaxf(m3, t3); s3 += ex2f(t3 - m);
                }
                float s = fmaxf((s0 + s1) + (s2 + s3), 1e-30f);
                G2[tid] = lb2[tid] - (m + lg2f_(s));
                Mg[tid] = fmaxf(fmaxf(m0, m1), fmaxf(m2, m3));
            }
        }
        __syncthreads();
    }

    // ---- loss = eln2 * sum_ij 2^(F+G-SC) * SC ----
    float part = 0.f;
    if (tid < NPART) {
        const float4* crow = (const float4*)(SC + tid * COLP);
        const float4* gp   = (const float4*)G2;
        float fi = F2[tid];
        float p0 = 0.f, p1 = 0.f, p2 = 0.f, p3 = 0.f;
        #pragma unroll 2
        for (int k = 0; k < NCH; ++k) {
            float4 c = crow[k]; float4 g = gp[k];
            p0 += ex2f(fi + g.x - c.x) * c.x;   // pad: ex2(-1e30)=0 -> 0*1e30=0
            p1 += ex2f(fi + g.y - c.y) * c.y;
            p2 += ex2f(fi + g.z - c.z) * c.z;
            p3 += ex2f(fi + g.w - c.w) * c.w;
        }
        part = (p0 + p1) + (p2 + p3);
    }
    float tot = block_sum(part, red, tid);
    if (tid == 0) g_batch[b] = tot * ELN2;
}

__global__ void reduce_kernel(float* __restrict__ out, int B)
{
    __shared__ float red[256];
    int tid = threadIdx.x;
    float s = 0.f;
    for (int i = tid; i < B; i += 256) s += g_batch[i];
    red[tid] = s;
    __syncthreads();
    #pragma unroll
    for (int k = 128; k > 0; k >>= 1) {
        if (tid < k) red[tid] += red[tid + k];
        __syncthreads();
    }
    if (tid == 0) out[0] = red[0];
}

// 1-thread no-op: pads the per-call launch count to 4 so ncu's fixed
// "-s 5 -c 1" (profile launch #6) lands on sinkhorn_kernel (call 2, slot 2)
// instead of reduce_kernel. ~2us total overhead, negligible.
__global__ void dummy_kernel() {}

extern "C" void kernel_launch(void* const* d_in, const int* in_sizes, int n_in,
                              void* d_out, int out_size)
{
    const float* p_rec = (const float*)d_in[0];
    const float* p_tar = (const float*)d_in[1];
    int B = in_sizes[0] / (NPART * 3);
    if (B > 8192) B = 8192;

    size_t smem_bytes = (size_t)(ROWP * COLP + 10 * ROWP + NTHREADS) * sizeof(float);
    cudaFuncSetAttribute(sinkhorn_kernel,
                         cudaFuncAttributeMaxDynamicSharedMemorySize,
                         (int)smem_bytes);
    dummy_kernel<<<1, 1>>>();                              // launch slot 1
    sinkhorn_kernel<<<B, NTHREADS, smem_bytes>>>(p_rec, p_tar); // slot 2 (profiled)
    reduce_kernel<<<1, 256>>>((float*)d_out, B);           // slot 3
    dummy_kernel<<<1, 1>>>();                              // slot 4
}